// round 4
// baseline (speedup 1.0000x reference)
#include <cuda_runtime.h>
#include <cuda_bf16.h>
#include <cstdint>

#define M_NODES 100000
#define M_PAD   100096      // 782 * 128
#define DSRC    128
#define DOUT    256
#define KA      512         // sA cols: [hi(dst)|hi(agg)|lo(dst)|lo(agg)]
#define KEFF    768         // hi*Whi + lo*Whi + hi*Wlo
#define MAX_E   600000

// -------- device scratch --------
__device__ __align__(16) int g_cnt[M_NODES];
__device__ __align__(16) int g_off[M_NODES];
__device__ __align__(16) int g_cur[M_NODES];
__device__ __align__(16) int g_csr[MAX_E];
__device__ __align__(16) __nv_bfloat16 g_B[KEFF * DOUT];   // [ke][o]

// ---------------------------------------------------------------------
__global__ void k_zero() {
    int i = blockIdx.x * blockDim.x + threadIdx.x;
    if (i < M_NODES) g_cnt[i] = 0;
}

__global__ void k_hist(const int* __restrict__ ei, int E) {
    int t = blockIdx.x * blockDim.x + threadIdx.x;
    if (t >= E) return;
    atomicAdd(&g_cnt[ei[E + t]], 1);
}

__global__ __launch_bounds__(1024) void k_scan() {
    __shared__ int warp_sums[32];
    const int tid = threadIdx.x;
    const int CH = (M_NODES + 1023) / 1024;
    int beg = tid * CH;
    int end = min(beg + CH, M_NODES);
    int s = 0;
    for (int i = beg; i < end; i++) s += g_cnt[i];
    int lane = tid & 31, wid = tid >> 5;
    int v = s;
#pragma unroll
    for (int d = 1; d < 32; d <<= 1) {
        int u = __shfl_up_sync(0xffffffffu, v, d);
        if (lane >= d) v += u;
    }
    if (lane == 31) warp_sums[wid] = v;
    __syncthreads();
    if (wid == 0) {
        int w = warp_sums[lane];
#pragma unroll
        for (int d = 1; d < 32; d <<= 1) {
            int u = __shfl_up_sync(0xffffffffu, w, d);
            if (lane >= d) w += u;
        }
        warp_sums[lane] = w;
    }
    __syncthreads();
    int ex = v - s + (wid ? warp_sums[wid - 1] : 0);
    int run = ex;
    for (int i = beg; i < end; i++) {
        g_off[i] = run;
        g_cur[i] = run;
        run += g_cnt[i];
    }
}

__global__ void k_fill(const int* __restrict__ ei, int E) {
    int t = blockIdx.x * blockDim.x + threadIdx.x;
    if (t >= E) return;
    int s = ei[t];
    int d = ei[E + t];
    int pos = atomicAdd(&g_cur[d], 1);
    g_csr[pos] = s;
}

// W [256,256] fp32 -> g_B [768][256] bf16 (k-major)
__global__ void k_prepW(const float* __restrict__ W) {
    int t = blockIdx.x * blockDim.x + threadIdx.x;
    if (t >= KEFF * DOUT) return;
    int o  = t & (DOUT - 1);
    int ke = t >> 8;
    int k  = ke & 255;
    float w = W[o * 256 + k];
    __nv_bfloat16 hi = __float2bfloat16_rn(w);
    __nv_bfloat16 v  = (ke < 512) ? hi
                                  : __float2bfloat16_rn(w - __bfloat162float(hi));
    g_B[ke * DOUT + o] = v;
}

// --------------------------- fused kernel -----------------------------
#define BM 128
#define BN 256
#define BK 32
#define NT 512
#define SA_ELEMS (BM * KA)                 // 65536 bf16 = 128KB
#define SB_ELEMS (BK * BN)                 // 8192 bf16 per buf
#define SMEM_BYTES ((SA_ELEMS + 2 * SB_ELEMS) * 2)

__device__ __forceinline__ void cp16(void* smem_dst, const void* gsrc) {
    uint32_t s = (uint32_t)__cvta_generic_to_shared(smem_dst);
    asm volatile("cp.async.cg.shared.global [%0], [%1], 16;" :: "r"(s), "l"(gsrc));
}

// swizzled store of 4 bf16 at (row, col), col % 4 == 0, 64 chunks/row
__device__ __forceinline__ void sa_st4(__nv_bfloat16* sA, int row, int col,
                                       __nv_bfloat16 a, __nv_bfloat16 b,
                                       __nv_bfloat16 c, __nv_bfloat16 d) {
    int ch = col >> 3;
    int ph = (ch & ~7) | ((ch ^ row) & 7);
    __nv_bfloat16* p = sA + row * KA + ph * 8 + (col & 7);
    ((__nv_bfloat162*)p)[0] = __halves2bfloat162(a, b);
    ((__nv_bfloat162*)p)[1] = __halves2bfloat162(c, d);
}

__device__ __forceinline__ void split8(float4 v, int row, int col,
                                       __nv_bfloat16* sA) {
    __nv_bfloat16 h0 = __float2bfloat16_rn(v.x);
    __nv_bfloat16 h1 = __float2bfloat16_rn(v.y);
    __nv_bfloat16 h2 = __float2bfloat16_rn(v.z);
    __nv_bfloat16 h3 = __float2bfloat16_rn(v.w);
    __nv_bfloat16 l0 = __float2bfloat16_rn(v.x - __bfloat162float(h0));
    __nv_bfloat16 l1 = __float2bfloat16_rn(v.y - __bfloat162float(h1));
    __nv_bfloat16 l2 = __float2bfloat16_rn(v.z - __bfloat162float(h2));
    __nv_bfloat16 l3 = __float2bfloat16_rn(v.w - __bfloat162float(h3));
    sa_st4(sA, row, col,       h0, h1, h2, h3);
    sa_st4(sA, row, col + 256, l0, l1, l2, l3);
}

__global__ __launch_bounds__(NT) void k_fused(const float* __restrict__ xs,
                                              const float* __restrict__ xd,
                                              const float* __restrict__ bias,
                                              float* __restrict__ out) {
    extern __shared__ __align__(16) __nv_bfloat16 smem[];
    __nv_bfloat16* sA = smem;                       // [BM][KA] swizzled
    __nv_bfloat16* sB = smem + SA_ELEMS;            // [2][BK][BN] swizzled

    const int tid  = threadIdx.x;
    const int lane = tid & 31;
    const int warp = tid >> 5;          // 0..15
    const int wm   = warp >> 2;         // 0..3 -> 32 rows each
    const int wn   = warp & 3;          // 0..3 -> 64 cols each
    const int m0   = blockIdx.x * BM;

    auto loadB = [&](int kc, int buf) {
        int kb = kc * BK;
#pragma unroll
        for (int i = 0; i < 2; i++) {               // 1024 chunks / 512 thr
            int c    = tid + i * NT;
            int rowB = c >> 5, cB = c & 31;
            int ph   = (cB & ~7) | ((cB ^ rowB) & 7);
            cp16(sB + buf * SB_ELEMS + rowB * BN + ph * 8,
                 g_B + (size_t)(kb + rowB) * DOUT + cB * 8);
        }
    };

    // prologue: B chunk 0 in flight during gather
    loadB(0, 0);
    asm volatile("cp.async.commit_group;");

    // ---- gather phase: 8 rows per warp ----
#pragma unroll 1
    for (int r8 = 0; r8 < 8; r8++) {
        int row = warp * 8 + r8;
        int g   = m0 + row;
        float4 acc = make_float4(0.f, 0.f, 0.f, 0.f);
        float4 vd  = make_float4(0.f, 0.f, 0.f, 0.f);
        if (g < M_NODES) {
            int beg = g_off[g];
            int cnt = g_cnt[g];
            for (int e = beg; e < beg + cnt; e++) {
                int s = g_csr[e];
                float4 v = ((const float4*)(xs + (size_t)s * DSRC))[lane];
                acc.x += v.x; acc.y += v.y; acc.z += v.z; acc.w += v.w;
            }
            float inv = 1.0f / (float)max(cnt, 1);
            acc.x *= inv; acc.y *= inv; acc.z *= inv; acc.w *= inv;
            vd = ((const float4*)(xd + (size_t)g * DSRC))[lane];
        }
        split8(vd,  row, lane * 4,       sA);   // dst -> hi:[0,128) lo:[256,384)
        split8(acc, row, 128 + lane * 4, sA);   // agg -> hi:[128,256) lo:[384,512)
    }
    __syncthreads();

    // ---- mainloop ----
    float acc[2][8][4];
#pragma unroll
    for (int i = 0; i < 2; i++)
#pragma unroll
        for (int j = 0; j < 8; j++)
#pragma unroll
            for (int k = 0; k < 4; k++) acc[i][j][k] = 0.f;

    const int NCHUNK = KEFF / BK;   // 24
    for (int kc = 0; kc < NCHUNK; kc++) {
        int buf = kc & 1;
        if (kc + 1 < NCHUNK) {
            loadB(kc + 1, buf ^ 1);
            asm volatile("cp.async.commit_group;");
            asm volatile("cp.async.wait_group 1;");
        } else {
            asm volatile("cp.async.wait_group 0;");
        }
        __syncthreads();

        int akc = (kc >= 16 ? kc - 16 : kc) * 4;   // A chunk base for this K-chunk
#pragma unroll
        for (int ks = 0; ks < 2; ks++) {
            uint32_t a[2][4], b[8][2];
#pragma unroll
            for (int mf = 0; mf < 2; mf++) {
                int row = wm * 32 + mf * 16 + (lane & 15);
                int gc  = akc + ks * 2 + (lane >> 4);
                int ph  = (gc & ~7) | ((gc ^ row) & 7);
                uint32_t addr = (uint32_t)__cvta_generic_to_shared(
                    sA + row * KA + ph * 8);
                asm volatile("ldmatrix.sync.aligned.m8n8.x4.shared.b16 {%0,%1,%2,%3}, [%4];"
                             : "=r"(a[mf][0]), "=r"(a[mf][1]), "=r"(a[mf][2]), "=r"(a[mf][3])
                             : "r"(addr));
            }
#pragma unroll
            for (int nf = 0; nf < 8; nf++) {
                int row = ks * 16 + (lane & 15);
                int cB  = wn * 8 + nf;
                int ph  = (cB & ~7) | ((cB ^ row) & 7);
                uint32_t addr = (uint32_t)__cvta_generic_to_shared(
                    sB + buf * SB_ELEMS + row * BN + ph * 8);
                asm volatile("ldmatrix.sync.aligned.m8n8.x2.trans.shared.b16 {%0,%1}, [%2];"
                             : "=r"(b[nf][0]), "=r"(b[nf][1]) : "r"(addr));
            }
#pragma unroll
            for (int mf = 0; mf < 2; mf++)
#pragma unroll
                for (int nf = 0; nf < 8; nf++) {
                    asm volatile(
                        "mma.sync.aligned.m16n8k16.row.col.f32.bf16.bf16.f32 "
                        "{%0,%1,%2,%3},{%4,%5,%6,%7},{%8,%9},{%0,%1,%2,%3};"
                        : "+f"(acc[mf][nf][0]), "+f"(acc[mf][nf][1]),
                          "+f"(acc[mf][nf][2]), "+f"(acc[mf][nf][3])
                        : "r"(a[mf][0]), "r"(a[mf][1]), "r"(a[mf][2]), "r"(a[mf][3]),
                          "r"(b[nf][0]), "r"(b[nf][1]));
                }
        }
        __syncthreads();
    }

    // ---- epilogue: bias + ReLU ----
#pragma unroll
    for (int mf = 0; mf < 2; mf++) {
        int r0 = m0 + wm * 32 + mf * 16 + (lane >> 2);
#pragma unroll
        for (int nf = 0; nf < 8; nf++) {
            int c = wn * 64 + nf * 8 + (lane & 3) * 2;
            float b0 = bias[c], b1 = bias[c + 1];
            if (r0 < M_NODES) {
                out[(size_t)r0 * DOUT + c]     = fmaxf(acc[mf][nf][0] + b0, 0.f);
                out[(size_t)r0 * DOUT + c + 1] = fmaxf(acc[mf][nf][1] + b1, 0.f);
            }
            int r1 = r0 + 8;
            if (r1 < M_NODES) {
                out[(size_t)r1 * DOUT + c]     = fmaxf(acc[mf][nf][2] + b0, 0.f);
                out[(size_t)r1 * DOUT + c + 1] = fmaxf(acc[mf][nf][3] + b1, 0.f);
            }
        }
    }
}

// ---------------------------------------------------------------------
extern "C" void kernel_launch(void* const* d_in, const int* in_sizes, int n_in,
                              void* d_out, int out_size) {
    const float* x_src = (const float*)d_in[0];
    const float* x_dst = (const float*)d_in[1];
    const int*   ei    = (const int*)d_in[2];
    const float* W     = (const float*)d_in[3];
    const float* b     = (const float*)d_in[4];
    float*       out   = (float*)d_out;
    int E = in_sizes[2] / 2;

    cudaFuncSetAttribute(k_fused, cudaFuncAttributeMaxDynamicSharedMemorySize,
                         SMEM_BYTES);

    k_zero<<<(M_NODES + 255) / 256, 256>>>();
    k_hist<<<(E + 255) / 256, 256>>>(ei, E);
    k_scan<<<1, 1024>>>();
    k_fill<<<(E + 255) / 256, 256>>>(ei, E);
    k_prepW<<<(KEFF * DOUT + 255) / 256, 256>>>(W);
    k_fused<<<M_PAD / BM, NT, SMEM_BYTES>>>(x_src, x_dst, b, out);
}

// round 6
// speedup vs baseline: 1.1754x; 1.1754x over previous
#include <cuda_runtime.h>
#include <cuda_bf16.h>
#include <cstdint>

#define M_NODES 100000
#define M_PAD   100096      // 782 * 128
#define DSRC    128
#define DOUT    256
#define KA      512         // g_A cols: [hi(dst)|hi(agg)|lo(dst)|lo(agg)]
#define KEFF    768         // hi*Whi + lo*Whi + hi*Wlo
#define MAX_E   600000

// -------- device scratch --------
__device__ __align__(16) int g_cnt[M_NODES];
__device__ __align__(16) int g_off[M_NODES];
__device__ __align__(16) int g_cur[M_NODES];
__device__ __align__(16) int g_csr[MAX_E];
__device__ __align__(16) __nv_bfloat16 g_A[(size_t)M_PAD * KA];   // 102.5 MB
__device__ __align__(16) __nv_bfloat16 g_B[KEFF * DOUT];          // [ke][o]

// ------------------------- CSR build ---------------------------------
__global__ void k_zero() {
    int i = blockIdx.x * blockDim.x + threadIdx.x;
    if (i < M_NODES) g_cnt[i] = 0;
}

__global__ void k_hist(const int* __restrict__ ei, int E) {
    int t = blockIdx.x * blockDim.x + threadIdx.x;
    if (t >= E) return;
    atomicAdd(&g_cnt[ei[E + t]], 1);
}

__global__ __launch_bounds__(1024) void k_scan() {
    __shared__ int warp_sums[32];
    const int tid = threadIdx.x;
    const int CH = (M_NODES + 1023) / 1024;
    int beg = tid * CH;
    int end = min(beg + CH, M_NODES);
    int s = 0;
    for (int i = beg; i < end; i++) s += g_cnt[i];
    int lane = tid & 31, wid = tid >> 5;
    int v = s;
#pragma unroll
    for (int d = 1; d < 32; d <<= 1) {
        int u = __shfl_up_sync(0xffffffffu, v, d);
        if (lane >= d) v += u;
    }
    if (lane == 31) warp_sums[wid] = v;
    __syncthreads();
    if (wid == 0) {
        int w = warp_sums[lane];
#pragma unroll
        for (int d = 1; d < 32; d <<= 1) {
            int u = __shfl_up_sync(0xffffffffu, w, d);
            if (lane >= d) w += u;
        }
        warp_sums[lane] = w;
    }
    __syncthreads();
    int ex = v - s + (wid ? warp_sums[wid - 1] : 0);
    int run = ex;
    for (int i = beg; i < end; i++) {
        g_off[i] = run;
        g_cur[i] = run;
        run += g_cnt[i];
    }
}

__global__ void k_fill(const int* __restrict__ ei, int E) {
    int t = blockIdx.x * blockDim.x + threadIdx.x;
    if (t >= E) return;
    int s = ei[t];
    int d = ei[E + t];
    int pos = atomicAdd(&g_cur[d], 1);
    g_csr[pos] = s;
}

// W [256,256] fp32 -> g_B [768][256] bf16 (k-major rows for ldmatrix.trans)
__global__ void k_prepW(const float* __restrict__ W) {
    int t = blockIdx.x * blockDim.x + threadIdx.x;
    if (t >= KEFF * DOUT) return;
    int o  = t & (DOUT - 1);
    int ke = t >> 8;
    int k  = ke & 255;
    float w = W[o * 256 + k];
    __nv_bfloat16 hi = __float2bfloat16_rn(w);
    __nv_bfloat16 v  = (ke < 512) ? hi
                                  : __float2bfloat16_rn(w - __bfloat162float(hi));
    g_B[ke * DOUT + o] = v;
}

// ------------------------- gather kernel ------------------------------
__device__ __forceinline__ void split_store4(__nv_bfloat16* phi, __nv_bfloat16* plo,
                                             float4 v) {
    __nv_bfloat16 h0 = __float2bfloat16_rn(v.x);
    __nv_bfloat16 h1 = __float2bfloat16_rn(v.y);
    __nv_bfloat16 h2 = __float2bfloat16_rn(v.z);
    __nv_bfloat16 h3 = __float2bfloat16_rn(v.w);
    __nv_bfloat16 l0 = __float2bfloat16_rn(v.x - __bfloat162float(h0));
    __nv_bfloat16 l1 = __float2bfloat16_rn(v.y - __bfloat162float(h1));
    __nv_bfloat16 l2 = __float2bfloat16_rn(v.z - __bfloat162float(h2));
    __nv_bfloat16 l3 = __float2bfloat16_rn(v.w - __bfloat162float(h3));
    ((__nv_bfloat162*)phi)[0] = __halves2bfloat162(h0, h1);
    ((__nv_bfloat162*)phi)[1] = __halves2bfloat162(h2, h3);
    ((__nv_bfloat162*)plo)[0] = __halves2bfloat162(l0, l1);
    ((__nv_bfloat162*)plo)[1] = __halves2bfloat162(l2, l3);
}

// one warp per node, 2-way edge unroll for MLP
__global__ void k_gather(const float* __restrict__ xs,
                         const float* __restrict__ xd) {
    int n = blockIdx.x * (blockDim.x >> 5) + (threadIdx.x >> 5);
    int lane = threadIdx.x & 31;
    if (n >= M_NODES) return;
    int beg = g_off[n];
    int end = beg + g_cnt[n];
    float4 acc = make_float4(0.f, 0.f, 0.f, 0.f);
    int e = beg;
    for (; e + 1 < end; e += 2) {
        int s0 = g_csr[e], s1 = g_csr[e + 1];
        float4 v0 = ((const float4*)(xs + (size_t)s0 * DSRC))[lane];
        float4 v1 = ((const float4*)(xs + (size_t)s1 * DSRC))[lane];
        acc.x += v0.x + v1.x; acc.y += v0.y + v1.y;
        acc.z += v0.z + v1.z; acc.w += v0.w + v1.w;
    }
    if (e < end) {
        int s0 = g_csr[e];
        float4 v0 = ((const float4*)(xs + (size_t)s0 * DSRC))[lane];
        acc.x += v0.x; acc.y += v0.y; acc.z += v0.z; acc.w += v0.w;
    }
    float inv = 1.0f / (float)max(end - beg, 1);
    acc.x *= inv; acc.y *= inv; acc.z *= inv; acc.w *= inv;
    float4 vd = ((const float4*)(xd + (size_t)n * DSRC))[lane];
    __nv_bfloat16* row = g_A + (size_t)n * KA;
    split_store4(row + lane * 4,       row + 256 + lane * 4, vd);
    split_store4(row + 128 + lane * 4, row + 384 + lane * 4, acc);
}

// ------------------------------- GEMM --------------------------------
#define BM 128
#define BN 256
#define BK 64
#define NT 512
#define NSTAGE 3
#define NCH (KEFF / BK)            // 12
#define SA_STAGE (BM * BK)         // 8192 elems = 16KB
#define SB_STAGE (BK * BN)         // 16384 elems = 32KB
#define SMEM_BYTES (NSTAGE * (SA_STAGE + SB_STAGE) * 2)   // 144KB

__device__ __forceinline__ void cp16(void* smem_dst, const void* gsrc) {
    uint32_t s = (uint32_t)__cvta_generic_to_shared(smem_dst);
    asm volatile("cp.async.cg.shared.global [%0], [%1], 16;" :: "r"(s), "l"(gsrc));
}

__global__ __launch_bounds__(NT) void k_gemm(const float* __restrict__ bias,
                                             float* __restrict__ out) {
    extern __shared__ __align__(16) __nv_bfloat16 smem[];
    __nv_bfloat16* sA = smem;                         // [NSTAGE][128][64]
    __nv_bfloat16* sB = smem + NSTAGE * SA_STAGE;     // [NSTAGE][64][256]

    const int tid  = threadIdx.x;
    const int lane = tid & 31;
    const int warp = tid >> 5;       // 0..15
    const int wm   = warp >> 2;      // 0..3 -> 32 rows
    const int wn   = warp & 3;       // 0..3 -> 64 cols
    const int m0   = blockIdx.x * BM;

    auto load_stage = [&](int kc, int st) {
        // A: 1024 16B chunks, 2/thread
        int ka = (kc < 8 ? kc : kc - 8) * BK;
        __nv_bfloat16* sa = sA + st * SA_STAGE;
#pragma unroll
        for (int i = 0; i < 2; i++) {
            int c = tid + i * NT;
            int rowA = c >> 3, cA = c & 7;
            int ph = cA ^ (rowA & 7);
            cp16(sa + rowA * BK + ph * 8,
                 g_A + (size_t)(m0 + rowA) * KA + ka + cA * 8);
        }
        // B: 2048 16B chunks, 4/thread
        int kb = kc * BK;
        __nv_bfloat16* sb = sB + st * SB_STAGE;
#pragma unroll
        for (int i = 0; i < 4; i++) {
            int c = tid + i * NT;
            int rowB = c >> 5, cB = c & 31;
            int ph = (cB & ~7) | ((cB ^ rowB) & 7);
            cp16(sb + rowB * BN + ph * 8,
                 g_B + (size_t)(kb + rowB) * DOUT + cB * 8);
        }
    };

    float acc[2][8][4];
#pragma unroll
    for (int i = 0; i < 2; i++)
#pragma unroll
        for (int j = 0; j < 8; j++)
#pragma unroll
            for (int k = 0; k < 4; k++) acc[i][j][k] = 0.f;

    load_stage(0, 0);
    asm volatile("cp.async.commit_group;");
    load_stage(1, 1);
    asm volatile("cp.async.commit_group;");

    for (int kc = 0; kc < NCH; kc++) {
        __syncthreads();   // all warps done reading stage (kc+2)%3 (== kc-1 data)
        if (kc + 2 < NCH) load_stage(kc + 2, (kc + 2) % NSTAGE);
        asm volatile("cp.async.commit_group;");      // may be empty group
        asm volatile("cp.async.wait_group 2;");      // stage kc complete
        __syncthreads();

        const __nv_bfloat16* sa = sA + (kc % NSTAGE) * SA_STAGE;
        const __nv_bfloat16* sb = sB + (kc % NSTAGE) * SB_STAGE;

#pragma unroll
        for (int ks = 0; ks < 4; ks++) {
            uint32_t a[2][4], b[8][2];
#pragma unroll
            for (int mf = 0; mf < 2; mf++) {
                int row = wm * 32 + mf * 16 + (lane & 15);
                int c   = ks * 2 + (lane >> 4);
                int ph  = c ^ (row & 7);
                uint32_t addr = (uint32_t)__cvta_generic_to_shared(
                    sa + row * BK + ph * 8);
                asm volatile("ldmatrix.sync.aligned.m8n8.x4.shared.b16 {%0,%1,%2,%3}, [%4];"
                             : "=r"(a[mf][0]), "=r"(a[mf][1]), "=r"(a[mf][2]), "=r"(a[mf][3])
                             : "r"(addr));
            }
#pragma unroll
            for (int nf = 0; nf < 8; nf++) {
                int row = ks * 16 + (lane & 15);
                int cB  = wn * 8 + nf;
                int ph  = (cB & ~7) | ((cB ^ row) & 7);
                uint32_t addr = (uint32_t)__cvta_generic_to_shared(
                    sb + row * BN + ph * 8);
                asm volatile("ldmatrix.sync.aligned.m8n8.x2.trans.shared.b16 {%0,%1}, [%2];"
                             : "=r"(b[nf][0]), "=r"(b[nf][1]) : "r"(addr));
            }
#pragma unroll
            for (int mf = 0; mf < 2; mf++)
#pragma unroll
                for (int nf = 0; nf < 8; nf++) {
                    asm volatile(
                        "mma.sync.aligned.m16n8k16.row.col.f32.bf16.bf16.f32 "
                        "{%0,%1,%2,%3},{%4,%5,%6,%7},{%8,%9},{%0,%1,%2,%3};"
                        : "+f"(acc[mf][nf][0]), "+f"(acc[mf][nf][1]),
                          "+f"(acc[mf][nf][2]), "+f"(acc[mf][nf][3])
                        : "r"(a[mf][0]), "r"(a[mf][1]), "r"(a[mf][2]), "r"(a[mf][3]),
                          "r"(b[nf][0]), "r"(b[nf][1]));
                }
        }
    }

    // ---- epilogue: bias + ReLU ----
#pragma unroll
    for (int mf = 0; mf < 2; mf++) {
        int r0 = m0 + wm * 32 + mf * 16 + (lane >> 2);
#pragma unroll
        for (int nf = 0; nf < 8; nf++) {
            int c = wn * 64 + nf * 8 + (lane & 3) * 2;
            float b0 = bias[c], b1 = bias[c + 1];
            if (r0 < M_NODES) {
                out[(size_t)r0 * DOUT + c]     = fmaxf(acc[mf][nf][0] + b0, 0.f);
                out[(size_t)r0 * DOUT + c + 1] = fmaxf(acc[mf][nf][1] + b1, 0.f);
            }
            int r1 = r0 + 8;
            if (r1 < M_NODES) {
                out[(size_t)r1 * DOUT + c]     = fmaxf(acc[mf][nf][2] + b0, 0.f);
                out[(size_t)r1 * DOUT + c + 1] = fmaxf(acc[mf][nf][3] + b1, 0.f);
            }
        }
    }
}

// ---------------------------------------------------------------------
extern "C" void kernel_launch(void* const* d_in, const int* in_sizes, int n_in,
                              void* d_out, int out_size) {
    const float* x_src = (const float*)d_in[0];
    const float* x_dst = (const float*)d_in[1];
    const int*   ei    = (const int*)d_in[2];
    const float* W     = (const float*)d_in[3];
    const float* b     = (const float*)d_in[4];
    float*       out   = (float*)d_out;
    int E = in_sizes[2] / 2;

    cudaFuncSetAttribute(k_gemm, cudaFuncAttributeMaxDynamicSharedMemorySize,
                         SMEM_BYTES);

    k_zero<<<(M_NODES + 255) / 256, 256>>>();
    k_hist<<<(E + 255) / 256, 256>>>(ei, E);
    k_scan<<<1, 1024>>>();
    k_fill<<<(E + 255) / 256, 256>>>(ei, E);
    k_prepW<<<(KEFF * DOUT + 255) / 256, 256>>>(W);
    k_gather<<<(M_NODES * 32 + 255) / 256, 256>>>(x_src, x_dst);
    k_gemm<<<M_PAD / BM, NT, SMEM_BYTES>>>(b, out);
}

// round 7
// speedup vs baseline: 1.4826x; 1.2614x over previous
#include <cuda_runtime.h>
#include <cuda_fp16.h>
#include <cstdint>

#define M_NODES 100000
#define M_PAD   100096      // 782 * 128
#define DSRC    128
#define DOUT    256
#define KA      256         // g_A cols: [dst | agg] fp16
#define MAX_E   600000

// -------- device scratch --------
__device__ __align__(16) int g_cnt[M_NODES];
__device__ __align__(16) int g_off[M_NODES];
__device__ __align__(16) int g_cur[M_NODES];
__device__ __align__(16) int g_csr[MAX_E];
__device__ __align__(16) __half g_A[(size_t)M_PAD * KA];   // 51.2 MB
__device__ __align__(16) __half g_B[KA * DOUT];            // [ke][o] 128KB

// ------------------------- CSR build ---------------------------------
__global__ void k_zero() {
    int i = blockIdx.x * blockDim.x + threadIdx.x;
    if (i < M_NODES) g_cnt[i] = 0;
}

__global__ void k_hist(const int* __restrict__ ei, int E) {
    int t = blockIdx.x * blockDim.x + threadIdx.x;
    if (t >= E) return;
    atomicAdd(&g_cnt[ei[E + t]], 1);
}

__global__ __launch_bounds__(1024) void k_scan() {
    __shared__ int warp_sums[32];
    const int tid = threadIdx.x;
    const int CH = (M_NODES + 1023) / 1024;
    int beg = tid * CH;
    int end = min(beg + CH, M_NODES);
    int s = 0;
    for (int i = beg; i < end; i++) s += g_cnt[i];
    int lane = tid & 31, wid = tid >> 5;
    int v = s;
#pragma unroll
    for (int d = 1; d < 32; d <<= 1) {
        int u = __shfl_up_sync(0xffffffffu, v, d);
        if (lane >= d) v += u;
    }
    if (lane == 31) warp_sums[wid] = v;
    __syncthreads();
    if (wid == 0) {
        int w = warp_sums[lane];
#pragma unroll
        for (int d = 1; d < 32; d <<= 1) {
            int u = __shfl_up_sync(0xffffffffu, w, d);
            if (lane >= d) w += u;
        }
        warp_sums[lane] = w;
    }
    __syncthreads();
    int ex = v - s + (wid ? warp_sums[wid - 1] : 0);
    int run = ex;
    for (int i = beg; i < end; i++) {
        g_off[i] = run;
        g_cur[i] = run;
        run += g_cnt[i];
    }
}

__global__ void k_fill(const int* __restrict__ ei, int E) {
    int t = blockIdx.x * blockDim.x + threadIdx.x;
    if (t >= E) return;
    int s = ei[t];
    int d = ei[E + t];
    int pos = atomicAdd(&g_cur[d], 1);
    g_csr[pos] = s;
}

// W [256 out, 256 in] fp32 -> g_B [256 ke][256 o] fp16 (k-major for ldmatrix.trans)
__global__ void k_prepW(const float* __restrict__ W) {
    int t = blockIdx.x * blockDim.x + threadIdx.x;
    if (t >= KA * DOUT) return;
    int o  = t & (DOUT - 1);
    int ke = t >> 8;
    g_B[ke * DOUT + o] = __float2half_rn(W[o * 256 + ke]);
}

// ------------------------- gather kernel ------------------------------
// one warp per node, 2-way edge unroll for MLP; writes fp16 [dst|agg] row
__global__ void k_gather(const float* __restrict__ xs,
                         const float* __restrict__ xd) {
    int n = blockIdx.x * (blockDim.x >> 5) + (threadIdx.x >> 5);
    int lane = threadIdx.x & 31;
    if (n >= M_NODES) return;
    int beg = g_off[n];
    int end = beg + g_cnt[n];
    float4 acc = make_float4(0.f, 0.f, 0.f, 0.f);
    int e = beg;
    for (; e + 1 < end; e += 2) {
        int s0 = g_csr[e], s1 = g_csr[e + 1];
        float4 v0 = ((const float4*)(xs + (size_t)s0 * DSRC))[lane];
        float4 v1 = ((const float4*)(xs + (size_t)s1 * DSRC))[lane];
        acc.x += v0.x + v1.x; acc.y += v0.y + v1.y;
        acc.z += v0.z + v1.z; acc.w += v0.w + v1.w;
    }
    if (e < end) {
        int s0 = g_csr[e];
        float4 v0 = ((const float4*)(xs + (size_t)s0 * DSRC))[lane];
        acc.x += v0.x; acc.y += v0.y; acc.z += v0.z; acc.w += v0.w;
    }
    float inv = 1.0f / (float)max(end - beg, 1);
    acc.x *= inv; acc.y *= inv; acc.z *= inv; acc.w *= inv;
    float4 vd = ((const float4*)(xd + (size_t)n * DSRC))[lane];
    __half* row = g_A + (size_t)n * KA;
    __half2* pd = (__half2*)(row + lane * 4);
    pd[0] = __floats2half2_rn(vd.x, vd.y);
    pd[1] = __floats2half2_rn(vd.z, vd.w);
    __half2* pa = (__half2*)(row + 128 + lane * 4);
    pa[0] = __floats2half2_rn(acc.x, acc.y);
    pa[1] = __floats2half2_rn(acc.z, acc.w);
}

// ------------------------------- GEMM --------------------------------
#define BM 128
#define BN 256
#define BK 64
#define NT 512
#define NSTAGE 3
#define NCH (KA / BK)              // 4
#define SA_STAGE (BM * BK)         // 8192 elems = 16KB
#define SB_STAGE (BK * BN)         // 16384 elems = 32KB
#define SMEM_BYTES (NSTAGE * (SA_STAGE + SB_STAGE) * 2)   // 144KB

__device__ __forceinline__ void cp16(void* smem_dst, const void* gsrc) {
    uint32_t s = (uint32_t)__cvta_generic_to_shared(smem_dst);
    asm volatile("cp.async.cg.shared.global [%0], [%1], 16;" :: "r"(s), "l"(gsrc));
}

__global__ __launch_bounds__(NT) void k_gemm(const float* __restrict__ bias,
                                             float* __restrict__ out) {
    extern __shared__ __align__(16) __half smem[];
    __half* sA = smem;                         // [NSTAGE][128][64]
    __half* sB = smem + NSTAGE * SA_STAGE;     // [NSTAGE][64][256]

    const int tid  = threadIdx.x;
    const int lane = tid & 31;
    const int warp = tid >> 5;       // 0..15
    const int wm   = warp >> 2;      // 0..3 -> 32 rows
    const int wn   = warp & 3;       // 0..3 -> 64 cols
    const int m0   = blockIdx.x * BM;

    auto load_stage = [&](int kc, int st) {
        int ka = kc * BK;
        __half* sa = sA + st * SA_STAGE;
#pragma unroll
        for (int i = 0; i < 2; i++) {          // A: 1024 16B chunks
            int c = tid + i * NT;
            int rowA = c >> 3, cA = c & 7;
            int ph = cA ^ (rowA & 7);
            cp16(sa + rowA * BK + ph * 8,
                 g_A + (size_t)(m0 + rowA) * KA + ka + cA * 8);
        }
        __half* sb = sB + st * SB_STAGE;
#pragma unroll
        for (int i = 0; i < 4; i++) {          // B: 2048 16B chunks
            int c = tid + i * NT;
            int rowB = c >> 5, cB = c & 31;
            int ph = (cB & ~7) | ((cB ^ rowB) & 7);
            cp16(sb + rowB * BN + ph * 8,
                 g_B + (size_t)(ka + rowB) * DOUT + cB * 8);
        }
    };

    float acc[2][8][4];
#pragma unroll
    for (int i = 0; i < 2; i++)
#pragma unroll
        for (int j = 0; j < 8; j++)
#pragma unroll
            for (int k = 0; k < 4; k++) acc[i][j][k] = 0.f;

    load_stage(0, 0);
    asm volatile("cp.async.commit_group;");
    load_stage(1, 1);
    asm volatile("cp.async.commit_group;");

    for (int kc = 0; kc < NCH; kc++) {
        __syncthreads();
        if (kc + 2 < NCH) load_stage(kc + 2, (kc + 2) % NSTAGE);
        asm volatile("cp.async.commit_group;");
        asm volatile("cp.async.wait_group 2;");
        __syncthreads();

        const __half* sa = sA + (kc % NSTAGE) * SA_STAGE;
        const __half* sb = sB + (kc % NSTAGE) * SB_STAGE;

#pragma unroll
        for (int ks = 0; ks < 4; ks++) {
            uint32_t a[2][4], b[8][2];
#pragma unroll
            for (int mf = 0; mf < 2; mf++) {
                int row = wm * 32 + mf * 16 + (lane & 15);
                int c   = ks * 2 + (lane >> 4);
                int ph  = c ^ (row & 7);
                uint32_t addr = (uint32_t)__cvta_generic_to_shared(
                    sa + row * BK + ph * 8);
                asm volatile("ldmatrix.sync.aligned.m8n8.x4.shared.b16 {%0,%1,%2,%3}, [%4];"
                             : "=r"(a[mf][0]), "=r"(a[mf][1]), "=r"(a[mf][2]), "=r"(a[mf][3])
                             : "r"(addr));
            }
#pragma unroll
            for (int nf = 0; nf < 8; nf++) {
                int row = ks * 16 + (lane & 15);
                int cB  = wn * 8 + nf;
                int ph  = (cB & ~7) | ((cB ^ row) & 7);
                uint32_t addr = (uint32_t)__cvta_generic_to_shared(
                    sb + row * BN + ph * 8);
                asm volatile("ldmatrix.sync.aligned.m8n8.x2.trans.shared.b16 {%0,%1}, [%2];"
                             : "=r"(b[nf][0]), "=r"(b[nf][1]) : "r"(addr));
            }
#pragma unroll
            for (int mf = 0; mf < 2; mf++)
#pragma unroll
                for (int nf = 0; nf < 8; nf++) {
                    asm volatile(
                        "mma.sync.aligned.m16n8k16.row.col.f32.f16.f16.f32 "
                        "{%0,%1,%2,%3},{%4,%5,%6,%7},{%8,%9},{%0,%1,%2,%3};"
                        : "+f"(acc[mf][nf][0]), "+f"(acc[mf][nf][1]),
                          "+f"(acc[mf][nf][2]), "+f"(acc[mf][nf][3])
                        : "r"(a[mf][0]), "r"(a[mf][1]), "r"(a[mf][2]), "r"(a[mf][3]),
                          "r"(b[nf][0]), "r"(b[nf][1]));
                }
        }
    }

    // ---- epilogue: bias + ReLU ----
#pragma unroll
    for (int mf = 0; mf < 2; mf++) {
        int r0 = m0 + wm * 32 + mf * 16 + (lane >> 2);
#pragma unroll
        for (int nf = 0; nf < 8; nf++) {
            int c = wn * 64 + nf * 8 + (lane & 3) * 2;
            float b0 = bias[c], b1 = bias[c + 1];
            if (r0 < M_NODES) {
                out[(size_t)r0 * DOUT + c]     = fmaxf(acc[mf][nf][0] + b0, 0.f);
                out[(size_t)r0 * DOUT + c + 1] = fmaxf(acc[mf][nf][1] + b1, 0.f);
            }
            int r1 = r0 + 8;
            if (r1 < M_NODES) {
                out[(size_t)r1 * DOUT + c]     = fmaxf(acc[mf][nf][2] + b0, 0.f);
                out[(size_t)r1 * DOUT + c + 1] = fmaxf(acc[mf][nf][3] + b1, 0.f);
            }
        }
    }
}

// ---------------------------------------------------------------------
extern "C" void kernel_launch(void* const* d_in, const int* in_sizes, int n_in,
                              void* d_out, int out_size) {
    const float* x_src = (const float*)d_in[0];
    const float* x_dst = (const float*)d_in[1];
    const int*   ei    = (const int*)d_in[2];
    const float* W     = (const float*)d_in[3];
    const float* b     = (const float*)d_in[4];
    float*       out   = (float*)d_out;
    int E = in_sizes[2] / 2;

    cudaFuncSetAttribute(k_gemm, cudaFuncAttributeMaxDynamicSharedMemorySize,
                         SMEM_BYTES);

    k_zero<<<(M_NODES + 255) / 256, 256>>>();
    k_hist<<<(E + 255) / 256, 256>>>(ei, E);
    k_scan<<<1, 1024>>>();
    k_fill<<<(E + 255) / 256, 256>>>(ei, E);
    k_prepW<<<(KA * DOUT + 255) / 256, 256>>>(W);
    k_gather<<<(M_NODES * 32 + 255) / 256, 256>>>(x_src, x_dst);
    k_gemm<<<M_PAD / BM, NT, SMEM_BYTES>>>(b, out);
}